// round 17
// baseline (speedup 1.0000x reference)
#include <cuda_runtime.h>

// SCVC: out[n, g*OG+o, p, q] = C[g,o]*x[n,g,p]*y[n,g,q] + a[n,g,o,p] + b[n,g,o,q]
//   a[p] = wA0*x[p-1] + wA1*x[p+1]  (zero boundary)
//   b[q] = wB0*y[q-1] + wB1*y[q+1]  (zero boundary)
// Shapes: N=8, G=8, OG=16, DX=DY=256. Output = 256 MiB fp32 -> HBM-store floor.
// R15: PT=64 (4096 blocks; prologue amortized 4x vs R13) + per-row (s, ap)
// precomputed in shared so the inner loop is 1 broadcast LDS.64 + 1 STG.128
// (l1tex was top utilization at 69.9%). Regs must stay ~32 (the proven
// invariant: amortize only while occupancy holds).

#define N_  8
#define G_  8
#define OG_ 16
#define DX_ 256
#define DY_ 256
#define PT  64   // p-rows per block

__global__ __launch_bounds__(256, 8) void scvc_kernel(
    const float* __restrict__ x,   // (N, G, DX)
    const float* __restrict__ y,   // (N, G, DY)
    const float* __restrict__ C,   // (G, OG)
    const float* __restrict__ wA,  // (G, OG, 2)
    const float* __restrict__ wB,  // (G, OG, 2)
    float* __restrict__ out)       // (N, G*OG, DX, DY)
{
    __shared__ float  sy[DY_];
    __shared__ float  sb[DY_];
    __shared__ float2 ssap[PT];   // (s = C*x[p], ap = wA0*x[p-1] + wA1*x[p+1])

    const int b  = blockIdx.x;
    const int pt = b & 3;             // DX_/PT = 4 tiles
    const int o  = (b >> 2) & 15;     // OG_ = 16
    const int g  = (b >> 6) & 7;      // G_  = 8
    const int n  = b >> 9;            // N_  = 8

    const int tid = threadIdx.x;
    const int ng = n * G_ + g;
    const int go = g * OG_ + o;

    const float* __restrict__ yrow = y + ng * DY_;
    const float* __restrict__ xrow = x + ng * DX_;

    const float wB0 = wB[go * 2 + 0];
    const float wB1 = wB[go * 2 + 1];
    const float Cgo = C[go];

    // Stage y row.
    sy[tid] = yrow[tid];

    // Per-row scalars for the 64 p-rows (independent of sy; before barrier).
    if (tid < PT) {
        const float wA0 = wA[go * 2 + 0];
        const float wA1 = wA[go * 2 + 1];
        const int p = pt * PT + tid;
        const float xp = xrow[p];
        const float xl = (p > 0)       ? xrow[p - 1] : 0.0f;
        const float xr = (p < DX_ - 1) ? xrow[p + 1] : 0.0f;
        ssap[tid] = make_float2(Cgo * xp, wA0 * xl + wA1 * xr);
    }
    __syncthreads();

    // b[q] from staged y.
    {
        const float yl = (tid > 0)       ? sy[tid - 1] : 0.0f;
        const float yr = (tid < DY_ - 1) ? sy[tid + 1] : 0.0f;
        sb[tid] = wB0 * yl + wB1 * yr;
    }
    __syncthreads();

    // Thread layout: r = row-within-4, c = float4 column (64 per row).
    const int r = tid >> 6;
    const int c = tid & 63;

    const float4 yv = reinterpret_cast<const float4*>(sy)[c];
    const float4 bv = reinterpret_cast<const float4*>(sb)[c];

    float* __restrict__ obase =
        out + ((size_t)ng * OG_ + o) * (size_t)(DX_ * DY_);

    #pragma unroll
    for (int it = 0; it < PT / 4; ++it) {
        const int p = pt * PT + it * 4 + r;
        const float2 sa = ssap[it * 4 + r];  // broadcast LDS.64 (warp-uniform)
        const float s  = sa.x;
        const float ap = sa.y;

        float4 v;
        v.x = fmaf(s, yv.x, ap + bv.x);
        v.y = fmaf(s, yv.y, ap + bv.y);
        v.z = fmaf(s, yv.z, ap + bv.z);
        v.w = fmaf(s, yv.w, ap + bv.w);

        // Streaming store: write-once output, bypass L2 persistence.
        __stcs(reinterpret_cast<float4*>(obase + (size_t)p * DY_) + c, v);
    }
}

extern "C" void kernel_launch(void* const* d_in, const int* in_sizes, int n_in,
                              void* d_out, int out_size)
{
    const float* x  = (const float*)d_in[0];
    const float* y  = (const float*)d_in[1];
    const float* C  = (const float*)d_in[2];
    const float* wA = (const float*)d_in[3];
    const float* wB = (const float*)d_in[4];
    float* out = (float*)d_out;

    const int nblocks = N_ * G_ * OG_ * (DX_ / PT);  // 4096
    scvc_kernel<<<nblocks, 256>>>(x, y, C, wA, wB, out);
}